// round 1
// baseline (speedup 1.0000x reference)
#include <cuda_runtime.h>
#include <cstdint>

#define N_NODES 1000000
#define N_EDGES 5000000

// Scratch (static device globals -- no allocation allowed)
__device__ float g_deg[N_NODES];
__device__ float g_dinv[N_NODES];
__device__ float g_xs[N_NODES];   // x * dinv   (layer-1 source values)
__device__ float g_ys[N_NODES];   // h2 * dinv  (layer-2 source values)
__device__ float g_S[N_NODES];    // scatter accumulator (reused both layers)
__device__ int   g_is64;          // 1 if edge_index is int64, 0 if int32

// ---------------------------------------------------------------------------
// Detect edge_index element width. int32 data misread as int64 gives values
// >= 2^32 with overwhelming probability (upper word is a random node id).
// 64 probe entries => false-detect probability ~ (1e-6)^64 ~ 0.
__global__ void k_detect(const long long* __restrict__ p) {
    int i = threadIdx.x;                 // 64 threads, reads bytes [0,512) - safe either way
    long long v = p[i];
    bool bad = (v < 0) || (v >= (long long)N_NODES);
    if (i == 0) g_is64 = 1;
    __syncthreads();
    if (bad) g_is64 = 0;
}

// ---------------------------------------------------------------------------
__global__ void k_init() {
    int i = blockIdx.x * blockDim.x + threadIdx.x;
    if (i < N_NODES) {
        g_deg[i] = 1.0f;   // self-loop
        g_S[i]   = 0.0f;
    }
}

// degree scatter: deg[dst] += 1
__global__ void k_deg(const void* __restrict__ ei) {
    long long e = (long long)blockIdx.x * blockDim.x + threadIdx.x;
    if (e >= N_EDGES) return;
    int d;
    if (g_is64) d = (int)((const long long*)ei)[N_EDGES + e];
    else        d = ((const int*)ei)[N_EDGES + e];
    atomicAdd(&g_deg[d], 1.0f);
}

// node pass 1: dinv, xs = x * dinv
__global__ void k_node1(const float* __restrict__ x) {
    int i = blockIdx.x * blockDim.x + threadIdx.x;
    if (i < N_NODES) {
        float dinv = rsqrtf(g_deg[i]);
        g_dinv[i] = dinv;
        g_xs[i]   = x[i] * dinv;
    }
}

// layer-1 edge scatter: S[dst] += xs[src]
__global__ void k_scatter1(const void* __restrict__ ei) {
    long long e = (long long)blockIdx.x * blockDim.x + threadIdx.x;
    if (e >= N_EDGES) return;
    int s, d;
    if (g_is64) {
        s = (int)((const long long*)ei)[e];
        d = (int)((const long long*)ei)[N_EDGES + e];
    } else {
        s = ((const int*)ei)[e];
        d = ((const int*)ei)[N_EDGES + e];
    }
    atomicAdd(&g_S[d], g_xs[s]);
}

// node pass 2: agg1 -> (relu @ W2 fold) -> ys; re-zero S for layer 2
__global__ void k_node2(const float* __restrict__ W1,
                        const float* __restrict__ b1,
                        const float* __restrict__ W2) {
    int i = blockIdx.x * blockDim.x + threadIdx.x;
    if (i < N_NODES) {
        float dinv = g_dinv[i];
        float agg  = dinv * (g_S[i] + g_xs[i]);   // layer-1 GCN output scale
        float h2 = 0.0f;
        #pragma unroll
        for (int f = 0; f < 16; f++) {
            h2 += fmaxf(fmaf(agg, W1[f], b1[f]), 0.0f) * W2[f];
        }
        g_ys[i] = h2 * dinv;
        g_S[i]  = 0.0f;
    }
}

// layer-2 edge scatter: S[dst] += ys[src]
__global__ void k_scatter2(const void* __restrict__ ei) {
    long long e = (long long)blockIdx.x * blockDim.x + threadIdx.x;
    if (e >= N_EDGES) return;
    int s, d;
    if (g_is64) {
        s = (int)((const long long*)ei)[e];
        d = (int)((const long long*)ei)[N_EDGES + e];
    } else {
        s = ((const int*)ei)[e];
        d = ((const int*)ei)[N_EDGES + e];
    }
    atomicAdd(&g_S[d], g_ys[s]);
}

// node pass 3: out = dinv*(S + ys) + b2
__global__ void k_node3(float* __restrict__ out, const float* __restrict__ b2) {
    int i = blockIdx.x * blockDim.x + threadIdx.x;
    if (i < N_NODES) {
        out[i] = g_dinv[i] * (g_S[i] + g_ys[i]) + b2[0];
    }
}

// ---------------------------------------------------------------------------
extern "C" void kernel_launch(void* const* d_in, const int* in_sizes, int n_in,
                              void* d_out, int out_size) {
    const float* x  = (const float*)d_in[0];
    const void*  ei = d_in[1];
    const float* W1 = (const float*)d_in[2];
    const float* b1 = (const float*)d_in[3];
    const float* W2 = (const float*)d_in[4];
    const float* b2 = (const float*)d_in[5];
    float* out = (float*)d_out;

    const int TB = 256;
    const int nodeBlocks = (N_NODES + TB - 1) / TB;
    const int edgeBlocks = (N_EDGES + TB - 1) / TB;

    k_detect<<<1, 64>>>((const long long*)ei);
    k_init<<<nodeBlocks, TB>>>();
    k_deg<<<edgeBlocks, TB>>>(ei);
    k_node1<<<nodeBlocks, TB>>>(x);
    k_scatter1<<<edgeBlocks, TB>>>(ei);
    k_node2<<<nodeBlocks, TB>>>(W1, b1, W2);
    k_scatter2<<<edgeBlocks, TB>>>(ei);
    k_node3<<<nodeBlocks, TB>>>(out, b2);
}

// round 2
// speedup vs baseline: 1.0341x; 1.0341x over previous
#include <cuda_runtime.h>
#include <cstdint>

#define N_NODES 1000000
#define N_EDGES 5000000

// Scratch (static device globals -- no allocation allowed)
__device__ float g_deg[N_NODES];
__device__ float g_dinv[N_NODES];
__device__ float g_xs[N_NODES];   // x * dinv   (layer-1 source values)
__device__ float g_ys[N_NODES];   // h2 * dinv  (layer-2 source values)
__device__ float g_S[N_NODES];    // scatter accumulator (reused both layers)
__device__ int   g_is64;          // 1 if edge_index is int64, 0 if int32

// ---------------------------------------------------------------------------
// Detect edge_index element width. int32 data misread as int64 gives values
// >= 2^32 (upper word is a random node id) with overwhelming probability.
__global__ void k_detect(const long long* __restrict__ p) {
    int i = threadIdx.x;                 // 64 threads; reads bytes [0,512) - safe either way
    long long v = p[i];
    bool bad = (v < 0) || (v >= (long long)N_NODES);
    if (i == 0) g_is64 = 1;
    __syncthreads();
    if (bad) g_is64 = 0;
}

// ---------------------------------------------------------------------------
// init: deg = 1 (self loop), S = 0.  float4, 4 nodes/thread.
__global__ void k_init() {
    int i = blockIdx.x * blockDim.x + threadIdx.x;   // 250k threads
    if (i < N_NODES / 4) {
        ((float4*)g_deg)[i] = make_float4(1.f, 1.f, 1.f, 1.f);
        ((float4*)g_S)[i]   = make_float4(0.f, 0.f, 0.f, 0.f);
    }
}

// ---------------------------------------------------------------------------
// degree scatter: deg[dst] += 1.  8 edges/thread, batched index loads.
__global__ void k_deg(const void* __restrict__ ei) {
    long long base = ((long long)blockIdx.x * blockDim.x + threadIdx.x) * 8;
    if (base >= N_EDGES) return;                     // N_EDGES % 8 == 0, no tail
    int d[8];
    if (g_is64) {
        const longlong2* p = (const longlong2*)((const long long*)ei + N_EDGES + base);
        longlong2 a = p[0], b = p[1], c = p[2], e = p[3];
        d[0]=(int)a.x; d[1]=(int)a.y; d[2]=(int)b.x; d[3]=(int)b.y;
        d[4]=(int)c.x; d[5]=(int)c.y; d[6]=(int)e.x; d[7]=(int)e.y;
    } else {
        const int4* p = (const int4*)((const int*)ei + N_EDGES + base);
        int4 a = p[0], b = p[1];
        d[0]=a.x; d[1]=a.y; d[2]=a.z; d[3]=a.w;
        d[4]=b.x; d[5]=b.y; d[6]=b.z; d[7]=b.w;
    }
    #pragma unroll
    for (int k = 0; k < 8; k++) atomicAdd(&g_deg[d[k]], 1.0f);
}

// ---------------------------------------------------------------------------
// node pass 1: dinv = rsqrt(deg), xs = x * dinv.  float4.
__global__ void k_node1(const float* __restrict__ x) {
    int i = blockIdx.x * blockDim.x + threadIdx.x;
    if (i < N_NODES / 4) {
        float4 dg = ((const float4*)g_deg)[i];
        float4 xv = ((const float4*)x)[i];
        float4 dv;
        dv.x = rsqrtf(dg.x); dv.y = rsqrtf(dg.y);
        dv.z = rsqrtf(dg.z); dv.w = rsqrtf(dg.w);
        ((float4*)g_dinv)[i] = dv;
        ((float4*)g_xs)[i] = make_float4(xv.x*dv.x, xv.y*dv.y, xv.z*dv.z, xv.w*dv.w);
    }
}

// ---------------------------------------------------------------------------
// edge scatter: S[dst] += vals[src].  4 edges/thread, batched loads first.
template <int WHICH>   // 0: vals = g_xs, 1: vals = g_ys
__global__ void k_scatter(const void* __restrict__ ei) {
    long long base = ((long long)blockIdx.x * blockDim.x + threadIdx.x) * 4;
    if (base >= N_EDGES) return;                     // N_EDGES % 4 == 0
    int s[4], d[4];
    if (g_is64) {
        const longlong2* ps = (const longlong2*)((const long long*)ei + base);
        const longlong2* pd = (const longlong2*)((const long long*)ei + N_EDGES + base);
        longlong2 s0 = ps[0], s1 = ps[1];
        longlong2 d0 = pd[0], d1 = pd[1];
        s[0]=(int)s0.x; s[1]=(int)s0.y; s[2]=(int)s1.x; s[3]=(int)s1.y;
        d[0]=(int)d0.x; d[1]=(int)d0.y; d[2]=(int)d1.x; d[3]=(int)d1.y;
    } else {
        int4 sv = *(const int4*)((const int*)ei + base);
        int4 dv = *(const int4*)((const int*)ei + N_EDGES + base);
        s[0]=sv.x; s[1]=sv.y; s[2]=sv.z; s[3]=sv.w;
        d[0]=dv.x; d[1]=dv.y; d[2]=dv.z; d[3]=dv.w;
    }
    const float* vals = WHICH ? g_ys : g_xs;
    float v[4];
    #pragma unroll
    for (int k = 0; k < 4; k++) v[k] = __ldg(&vals[s[k]]);   // 4 independent gathers
    #pragma unroll
    for (int k = 0; k < 4; k++) atomicAdd(&g_S[d[k]], v[k]);
}

// ---------------------------------------------------------------------------
// node pass 2: agg1 -> relu/W2 fold -> ys; re-zero S.  float4.
__global__ void k_node2(const float* __restrict__ W1,
                        const float* __restrict__ b1,
                        const float* __restrict__ W2) {
    int i = blockIdx.x * blockDim.x + threadIdx.x;
    if (i >= N_NODES / 4) return;

    float w1[16], bb[16], w2[16];
    #pragma unroll
    for (int f = 0; f < 16; f++) { w1[f] = W1[f]; bb[f] = b1[f]; w2[f] = W2[f]; }

    float4 Sv  = ((const float4*)g_S)[i];
    float4 xsv = ((const float4*)g_xs)[i];
    float4 dv  = ((const float4*)g_dinv)[i];

    float agg[4] = { dv.x*(Sv.x+xsv.x), dv.y*(Sv.y+xsv.y),
                     dv.z*(Sv.z+xsv.z), dv.w*(Sv.w+xsv.w) };
    float h2[4] = {0.f, 0.f, 0.f, 0.f};
    #pragma unroll
    for (int f = 0; f < 16; f++) {
        #pragma unroll
        for (int j = 0; j < 4; j++)
            h2[j] += fmaxf(fmaf(agg[j], w1[f], bb[f]), 0.0f) * w2[f];
    }
    ((float4*)g_ys)[i] = make_float4(h2[0]*dv.x, h2[1]*dv.y, h2[2]*dv.z, h2[3]*dv.w);
    ((float4*)g_S)[i]  = make_float4(0.f, 0.f, 0.f, 0.f);
}

// ---------------------------------------------------------------------------
// node pass 3: out = dinv*(S + ys) + b2.  float4.
__global__ void k_node3(float* __restrict__ out, const float* __restrict__ b2) {
    int i = blockIdx.x * blockDim.x + threadIdx.x;
    if (i < N_NODES / 4) {
        float bias = b2[0];
        float4 Sv = ((const float4*)g_S)[i];
        float4 yv = ((const float4*)g_ys)[i];
        float4 dv = ((const float4*)g_dinv)[i];
        ((float4*)out)[i] = make_float4(fmaf(dv.x, Sv.x + yv.x, bias),
                                        fmaf(dv.y, Sv.y + yv.y, bias),
                                        fmaf(dv.z, Sv.z + yv.z, bias),
                                        fmaf(dv.w, Sv.w + yv.w, bias));
    }
}

// ---------------------------------------------------------------------------
extern "C" void kernel_launch(void* const* d_in, const int* in_sizes, int n_in,
                              void* d_out, int out_size) {
    const float* x  = (const float*)d_in[0];
    const void*  ei = d_in[1];
    const float* W1 = (const float*)d_in[2];
    const float* b1 = (const float*)d_in[3];
    const float* W2 = (const float*)d_in[4];
    const float* b2 = (const float*)d_in[5];
    float* out = (float*)d_out;

    const int TB = 256;
    const int node4Blocks = (N_NODES / 4 + TB - 1) / TB;
    const int edge4Blocks = (N_EDGES / 4 + TB - 1) / TB;
    const int edge8Blocks = (N_EDGES / 8 + TB - 1) / TB;

    k_detect<<<1, 64>>>((const long long*)ei);
    k_init<<<node4Blocks, TB>>>();
    k_deg<<<edge8Blocks, TB>>>(ei);
    k_node1<<<node4Blocks, TB>>>(x);
    k_scatter<0><<<edge4Blocks, TB>>>(ei);
    k_node2<<<node4Blocks, TB>>>(W1, b1, W2);
    k_scatter<1><<<edge4Blocks, TB>>>(ei);
    k_node3<<<node4Blocks, TB>>>(out, b2);
}